// round 11
// baseline (speedup 1.0000x reference)
#include <cuda_runtime.h>
#include <cuda_fp16.h>
#include <math.h>
#include <cstdint>

#define SEQ   512
#define BATCH 64
#define INDIM 1024
#define HID   1024

// ---------------- device scratch (static: allowed) ----------------
__device__ __half g_Xhi[SEQ * BATCH * INDIM];
__device__ __half g_Xlo[SEQ * BATCH * INDIM];
__device__ __half g_Whi[HID * INDIM];
__device__ __half g_Wlo[HID * INDIM];
__device__ __half g_Hhi[2][BATCH * HID];
__device__ __half g_Hlo[2][BATCH * HID];
__device__ volatile unsigned g_arrive[128];

__global__ void init_sync_kernel() {
    g_arrive[threadIdx.x] = 0u;
}

// ---------------------------------------------------------------------------
__device__ __forceinline__ void cp_async16(void* smem_dst, const void* gsrc) {
    unsigned d = (unsigned)__cvta_generic_to_shared(smem_dst);
    asm volatile("cp.async.cg.shared.global [%0], [%1], 16;\n" :: "r"(d), "l"(gsrc));
}
__device__ __forceinline__ void cp_commit() { asm volatile("cp.async.commit_group;\n"); }
__device__ __forceinline__ void cp_wait0()  { asm volatile("cp.async.wait_group 0;\n"); }
__device__ __forceinline__ void cp_wait1()  { asm volatile("cp.async.wait_group 1;\n"); }

__device__ __forceinline__ float mask13(float v) {
    return __uint_as_float(__float_as_uint(v) & 0xFFFFE000u);
}

__device__ __forceinline__ void mma_f16(float* d,
                                        uint32_t a0, uint32_t a1, uint32_t a2, uint32_t a3,
                                        uint32_t b0, uint32_t b1) {
    asm volatile(
        "mma.sync.aligned.m16n8k16.row.col.f32.f16.f16.f32 "
        "{%0,%1,%2,%3}, {%4,%5,%6,%7}, {%8,%9}, {%0,%1,%2,%3};"
        : "+f"(d[0]), "+f"(d[1]), "+f"(d[2]), "+f"(d[3])
        : "r"(a0), "r"(a1), "r"(a2), "r"(a3), "r"(b0), "r"(b1));
}

// ---------------------------------------------------------------------------
// Split kernels: fp32 -> fp16 hi/lo planes
// ---------------------------------------------------------------------------
__global__ void split_x_kernel(const float* __restrict__ src) {
    int i = blockIdx.x * 256 + threadIdx.x;
    float4 v = ((const float4*)src)[i];
    float h0 = mask13(v.x), h1 = mask13(v.y), h2 = mask13(v.z), h3 = mask13(v.w);
    ((__half2*)g_Xhi)[2 * i]     = __floats2half2_rn(h0, h1);
    ((__half2*)g_Xhi)[2 * i + 1] = __floats2half2_rn(h2, h3);
    ((__half2*)g_Xlo)[2 * i]     = __floats2half2_rn(v.x - h0, v.y - h1);
    ((__half2*)g_Xlo)[2 * i + 1] = __floats2half2_rn(v.z - h2, v.w - h3);
}
__global__ void split_w_kernel(const float* __restrict__ src) {
    int i = blockIdx.x * 256 + threadIdx.x;
    float4 v = ((const float4*)src)[i];
    float h0 = mask13(v.x), h1 = mask13(v.y), h2 = mask13(v.z), h3 = mask13(v.w);
    ((__half2*)g_Whi)[2 * i]     = __floats2half2_rn(h0, h1);
    ((__half2*)g_Whi)[2 * i + 1] = __floats2half2_rn(h2, h3);
    ((__half2*)g_Wlo)[2 * i]     = __floats2half2_rn(v.x - h0, v.y - h1);
    ((__half2*)g_Wlo)[2 * i + 1] = __floats2half2_rn(v.z - h2, v.w - h3);
}

// ---------------------------------------------------------------------------
// Phase 1: C = x @ W_ih^T + bias. Pure fp16 3-pass MMA (unchanged).
// ---------------------------------------------------------------------------
#define P1P 40
__global__ __launch_bounds__(256) void gemm_xw_f16_kernel(
    const float* __restrict__ bih,
    const float* __restrict__ bhh,
    float* __restrict__ C)
{
    extern __shared__ __half sh[];
    __half* Ahi = sh;
    __half* Alo = sh + 10240;
    __half* Bhi = sh + 20480;
    __half* Blo = sh + 30720;

    const int tid    = threadIdx.x;
    const int lane   = tid & 31;
    const int wid    = tid >> 5;
    const int g      = lane >> 2;
    const int tig    = lane & 3;
    const int warp_m = wid & 1;
    const int warp_n = wid >> 1;
    const int bm     = blockIdx.y * 128;
    const int bn     = blockIdx.x * 128;

    float acc[4][4][4];
#pragma unroll
    for (int i = 0; i < 4; i++)
#pragma unroll
        for (int j = 0; j < 4; j++)
#pragma unroll
            for (int c = 0; c < 4; c++) acc[i][j][c] = 0.0f;

    const int srow = tid >> 2;
    const int sch  = tid & 3;

    auto stage = [&](int c) {
        const int bo = (c & 1) * 5120;
        const int kc = c * 32;
#pragma unroll
        for (int u = 0; u < 2; u++) {
            int row = srow + u * 64;
            size_t aoff = (size_t)(bm + row) * INDIM + kc + sch * 8;
            size_t boff = (size_t)(bn + row) * INDIM + kc + sch * 8;
            cp_async16(Ahi + bo + row * P1P + sch * 8, g_Xhi + aoff);
            cp_async16(Alo + bo + row * P1P + sch * 8, g_Xlo + aoff);
            cp_async16(Bhi + bo + row * P1P + sch * 8, g_Whi + boff);
            cp_async16(Blo + bo + row * P1P + sch * 8, g_Wlo + boff);
        }
        cp_commit();
    };

    stage(0);

    for (int c = 0; c < INDIM / 32; c++) {
        if (c + 1 < INDIM / 32) { stage(c + 1); cp_wait1(); }
        else                    { cp_wait0(); }
        __syncthreads();

        const int bo = (c & 1) * 5120;
        const __half* Aph = Ahi + bo + warp_m * 64 * P1P;
        const __half* Apl = Alo + bo + warp_m * 64 * P1P;
        const __half* Bph = Bhi + bo + warp_n * 32 * P1P;
        const __half* Bpl = Blo + bo + warp_n * 32 * P1P;

#pragma unroll
        for (int kg = 0; kg < 2; kg++) {
            const int ko = kg * 16 + 2 * tig;

            uint32_t ah[4][4], al[4][4];
#pragma unroll
            for (int mt = 0; mt < 4; mt++) {
                int base = (mt * 16 + g) * P1P + ko;
                ah[mt][0] = *(const uint32_t*)&Aph[base];
                ah[mt][1] = *(const uint32_t*)&Aph[base + 8 * P1P];
                ah[mt][2] = *(const uint32_t*)&Aph[base + 8];
                ah[mt][3] = *(const uint32_t*)&Aph[base + 8 * P1P + 8];
                al[mt][0] = *(const uint32_t*)&Apl[base];
                al[mt][1] = *(const uint32_t*)&Apl[base + 8 * P1P];
                al[mt][2] = *(const uint32_t*)&Apl[base + 8];
                al[mt][3] = *(const uint32_t*)&Apl[base + 8 * P1P + 8];
            }
            uint32_t bh[4][2], bl[4][2];
#pragma unroll
            for (int nt = 0; nt < 4; nt++) {
                int sb = (nt * 8 + g) * P1P + ko;
                bh[nt][0] = *(const uint32_t*)&Bph[sb];
                bh[nt][1] = *(const uint32_t*)&Bph[sb + 8];
                bl[nt][0] = *(const uint32_t*)&Bpl[sb];
                bl[nt][1] = *(const uint32_t*)&Bpl[sb + 8];
            }
#pragma unroll
            for (int mt = 0; mt < 4; mt++) {
#pragma unroll
                for (int nt = 0; nt < 4; nt++) {
                    mma_f16(acc[mt][nt], ah[mt][0], ah[mt][1], ah[mt][2], ah[mt][3],
                            bh[nt][0], bh[nt][1]);
                    mma_f16(acc[mt][nt], al[mt][0], al[mt][1], al[mt][2], al[mt][3],
                            bh[nt][0], bh[nt][1]);
                    mma_f16(acc[mt][nt], ah[mt][0], ah[mt][1], ah[mt][2], ah[mt][3],
                            bl[nt][0], bl[nt][1]);
                }
            }
        }
        __syncthreads();
    }

#pragma unroll
    for (int nt = 0; nt < 4; nt++) {
        const int n0 = bn + warp_n * 32 + nt * 8 + 2 * tig;
        const float bv0 = bih[n0] + bhh[n0];
        const float bv1 = bih[n0 + 1] + bhh[n0 + 1];
#pragma unroll
        for (int mt = 0; mt < 4; mt++) {
            const int m0 = bm + warp_m * 64 + mt * 16 + g;
            float2 lo2, hi2;
            lo2.x = acc[mt][nt][0] + bv0;
            lo2.y = acc[mt][nt][1] + bv1;
            hi2.x = acc[mt][nt][2] + bv0;
            hi2.y = acc[mt][nt][3] + bv1;
            *(float2*)(C + (size_t)m0 * HID + n0)       = lo2;
            *(float2*)(C + (size_t)(m0 + 8) * HID + n0) = hi2;
        }
    }
}

// ---------------------------------------------------------------------------
// Phase 2: persistent recurrence, (bt, jt) grid, single-shot staging,
//   per-bt-group distributed-flag barrier.
//   128 CTAs = (bt = bid&3) x (jt = bid>>2). CTA: m16 rows, n32 j cols.
//   8 warps = (nt = w>>1) x (kh = w&1); warp: m16 n8 k512 3-pass fp16 mma.
// SMEM halves: WHI[32][1032] | WLO | H hi[16][1048] | H lo[16][1048] | scr
// ---------------------------------------------------------------------------
#define RW  1032
#define RHP 1048
#define RSM_BYTES 201728
__global__ __launch_bounds__(256) void rnn_rec_f16_kernel(
    const float* __restrict__ W,
    float* __restrict__ out)
{
    extern __shared__ __half sh[];
    __half* WHI = sh;                        // 33024 halves
    __half* WLO = sh + 33024;
    __half* HSH = sh + 66048;                // hi plane [16][1048]
    __half* HSL = HSH + 16 * RHP;            // lo plane
    float* scratch = (float*)((char*)sh + 199168);   // [4][32][5] floats

    const int tid   = threadIdx.x;
    const int lane  = tid & 31;
    const int w     = tid >> 5;
    const int g     = lane >> 2;
    const int tig   = lane & 3;
    const int bt    = blockIdx.x & 3;
    const int jt    = blockIdx.x >> 2;
    const int jbase = jt * 32;
    const int mrow0 = bt * 16;
    const int nt    = w >> 1;
    const int kh    = w & 1;
    const int kbase = kh * 512;

    // ---- pre-split W rows jbase..jbase+31 (once) ----
    for (int i = tid; i < 32 * 1024; i += 256) {
        int r = i >> 10, col = i & 1023;
        float v = W[(size_t)(jbase + r) * HID + col];
        float h = mask13(v);
        WHI[r * RW + col] = __float2half_rn(h);
        WLO[r * RW + col] = __float2half_rn(v - h);
    }
    __syncthreads();

    // staging map: tid -> (plane, row, 8-of-128 16B segments)
    const int s_pl  = tid >> 7;          // 0 = hi, 1 = lo
    const int s_row = (tid >> 3) & 15;
    const int s_seg = tid & 7;

    for (int t = 0; t < SEQ; t++) {
        float* o0 = out + ((size_t)t * BATCH + mrow0 + g) * HID + jbase + nt * 8 + 2 * tig;
        float* o1 = o0 + (size_t)8 * HID;
        float2 xw0, xw1;
        if (kh == 0) {
            xw0 = *(const float2*)o0;
            xw1 = *(const float2*)o1;
        }

        float ahh[4] = {0.f, 0.f, 0.f, 0.f};
        float alh[4] = {0.f, 0.f, 0.f, 0.f};
        float ahl[4] = {0.f, 0.f, 0.f, 0.f};

        if (t > 0) {
            const int rp = (t - 1) & 1;
            const __half* gsrc = (s_pl == 0)
                ? g_Hhi[rp] + (size_t)(mrow0 + s_row) * HID
                : g_Hlo[rp] + (size_t)(mrow0 + s_row) * HID;
            __half* dst = (s_pl == 0 ? HSH : HSL) + s_row * RHP;

            // ---- single-shot staging: 16 cp.async16 per thread ----
#pragma unroll
            for (int u = 0; u < 16; u++) {
                int unit = s_seg + u * 8;          // 16B unit 0..127
                cp_async16(dst + unit * 8, gsrc + unit * 8);
            }
            cp_commit();
            cp_wait0();
            __syncthreads();

            // ---- free-running MMA loop: 32 x k16, no syncs ----
#pragma unroll 4
            for (int kk = 0; kk < 32; kk++) {
                const int ko = kbase + kk * 16 + 2 * tig;
                uint32_t ah0 = *(const uint32_t*)&HSH[g * RHP + ko];
                uint32_t ah1 = *(const uint32_t*)&HSH[(g + 8) * RHP + ko];
                uint32_t ah2 = *(const uint32_t*)&HSH[g * RHP + ko + 8];
                uint32_t ah3 = *(const uint32_t*)&HSH[(g + 8) * RHP + ko + 8];
                uint32_t al0 = *(const uint32_t*)&HSL[g * RHP + ko];
                uint32_t al1 = *(const uint32_t*)&HSL[(g + 8) * RHP + ko];
                uint32_t al2 = *(const uint32_t*)&HSL[g * RHP + ko + 8];
                uint32_t al3 = *(const uint32_t*)&HSL[(g + 8) * RHP + ko + 8];

                const int wrow = (nt * 8 + g) * RW + ko;
                uint32_t bh0 = *(const uint32_t*)&WHI[wrow];
                uint32_t bh1 = *(const uint32_t*)&WHI[wrow + 8];
                uint32_t bl0 = *(const uint32_t*)&WLO[wrow];
                uint32_t bl1 = *(const uint32_t*)&WLO[wrow + 8];

                mma_f16(ahh, ah0, ah1, ah2, ah3, bh0, bh1);
                mma_f16(alh, al0, al1, al2, al3, bh0, bh1);
                mma_f16(ahl, ah0, ah1, ah2, ah3, bl0, bl1);
            }
            __syncthreads();   // staging buffer reuse guard (next step)
        }

        // ---- combine k-halves via scratch, tanh, store fp32 + split fp16 ----
        if (kh == 1) {
            float* s = scratch + (nt * 32 + lane) * 5;
            s[0] = ahh[0] + alh[0] + ahl[0];
            s[1] = ahh[1] + alh[1] + ahl[1];
            s[2] = ahh[2] + alh[2] + ahl[2];
            s[3] = ahh[3] + alh[3] + ahl[3];
        }
        __syncthreads();
        if (kh == 0) {
            const float* s = scratch + (nt * 32 + lane) * 5;
            float v00 = tanhf(xw0.x + ahh[0] + alh[0] + ahl[0] + s[0]);
            float v01 = tanhf(xw0.y + ahh[1] + alh[1] + ahl[1] + s[1]);
            float v10 = tanhf(xw1.x + ahh[2] + alh[2] + ahl[2] + s[2]);
            float v11 = tanhf(xw1.y + ahh[3] + alh[3] + ahl[3] + s[3]);

            *(float2*)o0 = make_float2(v00, v01);
            *(float2*)o1 = make_float2(v10, v11);

            const int wp = t & 1;
            __half* Hh = g_Hhi[wp];
            __half* Hl = g_Hlo[wp];
            const size_t i0 = (size_t)(mrow0 + g) * HID + jbase + nt * 8 + 2 * tig;
            const size_t i1 = i0 + (size_t)8 * HID;
            float h00 = mask13(v00), h01 = mask13(v01);
            float h10 = mask13(v10), h11 = mask13(v11);
            *(__half2*)(Hh + i0) = __floats2half2_rn(h00, h01);
            *(__half2*)(Hl + i0) = __floats2half2_rn(v00 - h00, v01 - h01);
            *(__half2*)(Hh + i1) = __floats2half2_rn(h10, h11);
            *(__half2*)(Hl + i1) = __floats2half2_rn(v10 - h10, v11 - h11);
        }

        // ---- bt-group barrier: distributed flags, warp 0 polls 32 members --
        if (t < SEQ - 1) {
            __syncthreads();                 // all epilogue stores issued
            if (tid == 0) {
                __threadfence();
                g_arrive[blockIdx.x] = (unsigned)(t + 1);
            }
            if (w == 0) {
                volatile unsigned* f = &g_arrive[4 * lane + bt];
                while (*f < (unsigned)(t + 1)) { }
                __threadfence();
            }
            __syncthreads();
        }
    }
}

// ---------------------------------------------------------------------------
__global__ void copy_hn_kernel(const float* __restrict__ src,
                               float* __restrict__ dst)
{
    int i = blockIdx.x * blockDim.x + threadIdx.x;
    float4 v = ((const float4*)src)[i];
    ((float4*)dst)[i] = v;
}

// ---------------------------------------------------------------------------
extern "C" void kernel_launch(void* const* d_in, const int* in_sizes, int n_in,
                              void* d_out, int out_size)
{
    (void)in_sizes; (void)n_in; (void)out_size;
    const float* x    = (const float*)d_in[0];
    const float* W_ih = (const float*)d_in[1];
    const float* W_hh = (const float*)d_in[2];
    const float* b_ih = (const float*)d_in[3];
    const float* b_hh = (const float*)d_in[4];
    float* out = (float*)d_out;

    cudaFuncSetAttribute(gemm_xw_f16_kernel,
                         cudaFuncAttributeMaxDynamicSharedMemorySize, 81920);
    cudaFuncSetAttribute(rnn_rec_f16_kernel,
                         cudaFuncAttributeMaxDynamicSharedMemorySize, RSM_BYTES);

    init_sync_kernel<<<1, 128>>>();

    split_x_kernel<<<(SEQ * BATCH * INDIM / 4) / 256, 256>>>(x);
    split_w_kernel<<<(HID * INDIM / 4) / 256, 256>>>(W_ih);

    dim3 g1(HID / 128, (SEQ * BATCH) / 128);
    gemm_xw_f16_kernel<<<g1, 256, 81920>>>(b_ih, b_hh, out);

    rnn_rec_f16_kernel<<<128, 256, RSM_BYTES>>>(W_hh, out);

    copy_hn_kernel<<<(BATCH * HID / 4) / 256, 256>>>(
        out + (size_t)(SEQ - 1) * BATCH * HID,
        out + (size_t)SEQ * BATCH * HID);
}